// round 1
// baseline (speedup 1.0000x reference)
#include <cuda_runtime.h>
#include <math.h>

#define NB 64
#define NS 4096
#define NC 128
#define KTOP 64

// 128 MB scratch holding the (B, C, S) transposed data; FFT operates in-place on rows.
__device__ float g_tr[(size_t)NB * NC * NS];
// Twiddle table: g_tw[m] = exp(-2*pi*i*m/4096), m in [0, 4096)
__device__ float2 g_tw[NS];

__device__ __forceinline__ int drev4(int p) {
    // base-4 digit reversal of a 12-bit index (involution)
    unsigned br = __brev((unsigned)p) >> 20;               // 12-bit bit reversal
    return (int)(((br & 0x555u) << 1) | ((br & 0xAAAu) >> 1));
}

__device__ __forceinline__ float2 cmul(float2 a, float2 b) {
    return make_float2(a.x * b.x - a.y * b.y, a.x * b.y + a.y * b.x);
}

// ---------------- twiddle init (fp64-accurate, tiny) ----------------
__global__ void k_tw() {
    int m = blockIdx.x * blockDim.x + threadIdx.x;
    if (m < NS) {
        double ang = -2.0 * 3.14159265358979323846 * (double)m / (double)NS;
        g_tw[m] = make_float2((float)cos(ang), (float)sin(ang));
    }
}

// ---------------- transpose (B,S,C) -> scratch (B,C,S) ----------------
__global__ void k_t1(const float* __restrict__ in) {
    __shared__ float tile[32][33];
    int b  = blockIdx.z;
    int c0 = blockIdx.x * 32;
    int s0 = blockIdx.y * 32;
    #pragma unroll
    for (int i = threadIdx.y; i < 32; i += 8) {
        tile[i][threadIdx.x] = in[((size_t)b * NS + (s0 + i)) * NC + (c0 + threadIdx.x)];
    }
    __syncthreads();
    #pragma unroll
    for (int i = threadIdx.y; i < 32; i += 8) {
        g_tr[((size_t)b * NC + (c0 + i)) * NS + (s0 + threadIdx.x)] = tile[threadIdx.x][i];
    }
}

// ---------------- transpose scratch (B,C,S) -> out (B,S,C) ----------------
__global__ void k_t3(float* __restrict__ out) {
    __shared__ float tile[32][33];
    int b  = blockIdx.z;
    int c0 = blockIdx.x * 32;
    int s0 = blockIdx.y * 32;
    #pragma unroll
    for (int i = threadIdx.y; i < 32; i += 8) {
        tile[i][threadIdx.x] = g_tr[((size_t)b * NC + (c0 + i)) * NS + (s0 + threadIdx.x)];
    }
    __syncthreads();
    #pragma unroll
    for (int i = threadIdx.y; i < 32; i += 8) {
        out[((size_t)b * NS + (s0 + i)) * NC + (c0 + threadIdx.x)] = tile[threadIdx.x][i];
    }
}

// ---------------- per-signal: FFT -> top-64 mask -> inverse FFT ----------------
__global__ __launch_bounds__(256) void k_fft() {
    __shared__ float2 X[NS];
    __shared__ unsigned hist[256];
    __shared__ unsigned s_prefix;
    __shared__ unsigned s_need;

    const int tid = threadIdx.x;
    float* rowp = g_tr + (size_t)blockIdx.x * NS;

    // load row (vectorized)
    const float4* rp4 = (const float4*)rowp;
    #pragma unroll
    for (int i = tid; i < NS / 4; i += 256) {
        float4 v = rp4[i];
        X[4 * i + 0] = make_float2(v.x, 0.f);
        X[4 * i + 1] = make_float2(v.y, 0.f);
        X[4 * i + 2] = make_float2(v.z, 0.f);
        X[4 * i + 3] = make_float2(v.w, 0.f);
    }
    if (tid == 0) { s_prefix = 0u; s_need = KTOP; }
    __syncthreads();

    // ---- forward: radix-4 DIF (natural in -> base-4-digit-reversed out) ----
    #pragma unroll
    for (int ls = 10; ls >= 0; ls -= 2) {
        const int s = 1 << ls;
        const int f = 1 << (10 - ls);   // twiddle index stride: m = t * f
        #pragma unroll
        for (int mm = 0; mm < 4; mm++) {
            int j    = tid + 256 * mm;
            int t    = j & (s - 1);
            int blk  = j >> ls;
            int base = blk * (4 * s) + t;
            float2 a = X[base];
            float2 b = X[base + s];
            float2 c = X[base + 2 * s];
            float2 d = X[base + 3 * s];
            float2 acp = make_float2(a.x + c.x, a.y + c.y);
            float2 acm = make_float2(a.x - c.x, a.y - c.y);
            float2 bdp = make_float2(b.x + d.x, b.y + d.y);
            float2 bdm = make_float2(b.x - d.x, b.y - d.y);
            float2 y0 = make_float2(acp.x + bdp.x, acp.y + bdp.y);
            float2 y2 = make_float2(acp.x - bdp.x, acp.y - bdp.y);
            float2 y1 = make_float2(acm.x + bdm.y, acm.y - bdm.x);  // acm - i*bdm
            float2 y3 = make_float2(acm.x - bdm.y, acm.y + bdm.x);  // acm + i*bdm
            float2 w1 = g_tw[t * f];
            float2 w2 = g_tw[2 * t * f];
            float2 w3 = g_tw[3 * t * f];
            X[base]         = y0;
            X[base + s]     = cmul(y1, w1);
            X[base + 2 * s] = cmul(y2, w2);
            X[base + 3 * s] = cmul(y3, w3);
        }
        __syncthreads();
    }

    // ---- top-64 pivot over |X|^2 of rfft bins 0..2048 (4-pass radix select) ----
    unsigned prefmask = 0u;
    for (int pass = 0; pass < 4; pass++) {
        const int shift = 24 - 8 * pass;
        hist[tid] = 0u;
        __syncthreads();
        const unsigned pref = s_prefix;
        #pragma unroll
        for (int p = tid; p < NS; p += 256) {
            int k = drev4(p);
            if (k <= NS / 2) {
                float2 v = X[p];
                float m2 = v.x * v.x + v.y * v.y;
                unsigned u = __float_as_uint(m2);
                if ((u & prefmask) == pref)
                    atomicAdd(&hist[(u >> shift) & 255], 1u);
            }
        }
        __syncthreads();
        if (tid == 0) {
            unsigned need = s_need, acc = 0;
            for (int bkt = 255; bkt >= 0; bkt--) {
                unsigned cnt = hist[bkt];
                if (acc + cnt >= need) {
                    s_need   = need - acc;
                    s_prefix = pref | ((unsigned)bkt << shift);
                    break;
                }
                acc += cnt;
            }
        }
        prefmask = 0xFFFFFFFFu << shift;
        __syncthreads();
    }
    const float pivot = __uint_as_float(s_prefix);

    // ---- Hermitian-symmetric mask: decide from canonical bin, then zero ----
    bool keep[16];
    #pragma unroll
    for (int mm = 0; mm < 16; mm++) {
        int p  = tid + 256 * mm;
        int k  = drev4(p);
        int km = (k <= NS / 2) ? k : (NS - k);
        float2 v = X[drev4(km)];
        float m2 = v.x * v.x + v.y * v.y;
        keep[mm] = (m2 >= pivot);
    }
    __syncthreads();
    #pragma unroll
    for (int mm = 0; mm < 16; mm++) {
        int p = tid + 256 * mm;
        if (!keep[mm]) X[p] = make_float2(0.f, 0.f);
    }
    __syncthreads();

    // ---- inverse: radix-4 DIT (digit-reversed in -> natural out), conj twiddles ----
    #pragma unroll
    for (int ls = 0; ls <= 10; ls += 2) {
        const int s = 1 << ls;
        const int f = 1 << (10 - ls);
        #pragma unroll
        for (int mm = 0; mm < 4; mm++) {
            int j    = tid + 256 * mm;
            int t    = j & (s - 1);
            int blk  = j >> ls;
            int base = blk * (4 * s) + t;
            float2 a = X[base];
            float2 b = X[base + s];
            float2 c = X[base + 2 * s];
            float2 d = X[base + 3 * s];
            float2 w1t = g_tw[t * f];
            float2 w2t = g_tw[2 * t * f];
            float2 w3t = g_tw[3 * t * f];
            float2 w1 = make_float2(w1t.x, -w1t.y);   // conjugate for inverse
            float2 w2 = make_float2(w2t.x, -w2t.y);
            float2 w3 = make_float2(w3t.x, -w3t.y);
            b = cmul(b, w1);
            c = cmul(c, w2);
            d = cmul(d, w3);
            float2 pp = make_float2(a.x + c.x, a.y + c.y);
            float2 mmv = make_float2(a.x - c.x, a.y - c.y);
            float2 qq = make_float2(b.x + d.x, b.y + d.y);
            float2 rr = make_float2(b.x - d.x, b.y - d.y);
            X[base]         = make_float2(pp.x + qq.x, pp.y + qq.y);
            X[base + 2 * s] = make_float2(pp.x - qq.x, pp.y - qq.y);
            X[base + s]     = make_float2(mmv.x - rr.y, mmv.y + rr.x);  // mm + i*rr
            X[base + 3 * s] = make_float2(mmv.x + rr.y, mmv.y - rr.x);  // mm - i*rr
        }
        __syncthreads();
    }

    // store real part / N (in-place on scratch row)
    float4* wp4 = (float4*)rowp;
    const float inv_n = 1.0f / (float)NS;
    #pragma unroll
    for (int i = tid; i < NS / 4; i += 256) {
        float4 v;
        v.x = X[4 * i + 0].x * inv_n;
        v.y = X[4 * i + 1].x * inv_n;
        v.z = X[4 * i + 2].x * inv_n;
        v.w = X[4 * i + 3].x * inv_n;
        wp4[i] = v;
    }
}

extern "C" void kernel_launch(void* const* d_in, const int* in_sizes, int n_in,
                              void* d_out, int out_size) {
    const float* in = (const float*)d_in[0];
    float* out = (float*)d_out;

    k_tw<<<(NS + 255) / 256, 256>>>();

    dim3 bt(32, 8);
    dim3 gt(NC / 32, NS / 32, NB);
    k_t1<<<gt, bt>>>(in);

    k_fft<<<NB * NC, 256>>>();

    k_t3<<<gt, bt>>>(out);
}

// round 2
// speedup vs baseline: 1.5138x; 1.5138x over previous
#include <cuda_runtime.h>
#include <math.h>

#define NB 64
#define NS 4096
#define NC 128
#define KTOP 64

#define PHY(p) ((p) ^ (((p) >> 4) & 15))

// 128 MB scratch holding the (B, C, S) transposed data; FFT operates in-place on rows.
__device__ float g_tr[(size_t)NB * NC * NS];
// Twiddle table: g_tw[m] = exp(-2*pi*i*m/4096)
__device__ float2 g_tw[NS];

__device__ __forceinline__ int drev4(int p) {
    unsigned br = __brev((unsigned)p) >> 20;               // 12-bit bit reversal
    return (int)(((br & 0x555u) << 1) | ((br & 0xAAAu) >> 1));
}

__device__ __forceinline__ float2 cmul(float2 a, float2 b) {
    return make_float2(a.x * b.x - a.y * b.y, a.x * b.y + a.y * b.x);
}
__device__ __forceinline__ float2 cmulc(float2 a, float2 b) {   // a * conj(b)
    return make_float2(a.x * b.x + a.y * b.y, a.y * b.x - a.x * b.y);
}

// W16^k = exp(-2*pi*i*k/16); constant-index after unroll -> immediates
__device__ __forceinline__ float2 w16c(int idx) {
    const float cr[16] = { 1.f,  0.9238795325112867f,  0.7071067811865476f,  0.3826834323650898f,
                           0.f, -0.3826834323650898f, -0.7071067811865476f, -0.9238795325112867f,
                          -1.f, -0.9238795325112867f, -0.7071067811865476f, -0.3826834323650898f,
                           0.f,  0.3826834323650898f,  0.7071067811865476f,  0.9238795325112867f };
    const float ci[16] = { 0.f, -0.3826834323650898f, -0.7071067811865476f, -0.9238795325112867f,
                          -1.f, -0.9238795325112867f, -0.7071067811865476f, -0.3826834323650898f,
                           0.f,  0.3826834323650898f,  0.7071067811865476f,  0.9238795325112867f,
                           1.f,  0.9238795325112867f,  0.7071067811865476f,  0.3826834323650898f };
    return make_float2(cr[idx], ci[idx]);
}

// forward DFT4 (omega = -i): outputs Y0..Y3 in a,b,c,d
__device__ __forceinline__ void bf4f(float2& a, float2& b, float2& c, float2& d) {
    float2 acp = make_float2(a.x + c.x, a.y + c.y);
    float2 acm = make_float2(a.x - c.x, a.y - c.y);
    float2 bdp = make_float2(b.x + d.x, b.y + d.y);
    float2 bdm = make_float2(b.x - d.x, b.y - d.y);
    a = make_float2(acp.x + bdp.x, acp.y + bdp.y);
    b = make_float2(acm.x + bdm.y, acm.y - bdm.x);   // acm - i*bdm
    c = make_float2(acp.x - bdp.x, acp.y - bdp.y);
    d = make_float2(acm.x - bdm.y, acm.y + bdm.x);   // acm + i*bdm
}
// inverse DFT4 (omega = +i)
__device__ __forceinline__ void bf4i(float2& a, float2& b, float2& c, float2& d) {
    float2 acp = make_float2(a.x + c.x, a.y + c.y);
    float2 acm = make_float2(a.x - c.x, a.y - c.y);
    float2 bdp = make_float2(b.x + d.x, b.y + d.y);
    float2 bdm = make_float2(b.x - d.x, b.y - d.y);
    a = make_float2(acp.x + bdp.x, acp.y + bdp.y);
    b = make_float2(acm.x - bdm.y, acm.y + bdm.x);   // acm + i*bdm
    c = make_float2(acp.x - bdp.x, acp.y - bdp.y);
    d = make_float2(acm.x + bdm.y, acm.y - bdm.x);
}

// 16-pt DIF in registers: input natural, output v[i] = Y_{rev2(i)}
__device__ __forceinline__ void sixteen_fwd(float2* v) {
    #pragma unroll
    for (int c = 0; c < 4; c++) {
        bf4f(v[c], v[c + 4], v[c + 8], v[c + 12]);
        if (c) {
            #pragma unroll
            for (int m = 1; m < 4; m++)
                v[c + 4 * m] = cmul(v[c + 4 * m], w16c(c * m));
        }
    }
    #pragma unroll
    for (int b = 0; b < 4; b++)
        bf4i(v[4 * b + 0], v[4 * b + 1], v[4 * b + 2], v[4 * b + 3]) , (void)0;
}
// NOTE: level B of the forward must be the FORWARD butterfly; fix below.
__device__ __forceinline__ void sixteen_fwd_fix(float2* v) {
    #pragma unroll
    for (int c = 0; c < 4; c++) {
        bf4f(v[c], v[c + 4], v[c + 8], v[c + 12]);
        if (c) {
            #pragma unroll
            for (int m = 1; m < 4; m++)
                v[c + 4 * m] = cmul(v[c + 4 * m], w16c(c * m));
        }
    }
    #pragma unroll
    for (int b = 0; b < 4; b++)
        bf4f(v[4 * b + 0], v[4 * b + 1], v[4 * b + 2], v[4 * b + 3]);
}

// 16-pt DIT inverse: input v[i] = Z_{rev2(i)} (ext twiddles pre-applied), output natural
__device__ __forceinline__ void sixteen_inv(float2* v) {
    #pragma unroll
    for (int b = 0; b < 4; b++)
        bf4i(v[4 * b + 0], v[4 * b + 1], v[4 * b + 2], v[4 * b + 3]);
    #pragma unroll
    for (int c = 1; c < 4; c++) {
        #pragma unroll
        for (int m = 1; m < 4; m++)
            v[c + 4 * m] = cmulc(v[c + 4 * m], w16c(c * m));
    }
    #pragma unroll
    for (int c = 0; c < 4; c++)
        bf4i(v[c], v[c + 4], v[c + 8], v[c + 12]);
}

template<int S, int G>
__device__ __forceinline__ void fwd_stage(float2* Xs, int tid) {
    int blk, t;
    if (S == 256)      { blk = 0;         t = tid;      }
    else if (S == 16)  { blk = tid >> 4;  t = tid & 15; }
    else               { blk = tid;       t = 0;        }
    int base = blk * 16 * S + t;
    float2 v[16];
    #pragma unroll
    for (int i = 0; i < 16; i++) v[i] = Xs[PHY(base + i * S)];
    sixteen_fwd_fix(v);
    #pragma unroll
    for (int i = 0; i < 16; i++) {
        int r = ((i & 3) << 2) | (i >> 2);
        float2 o = v[i];
        if (S != 1 && r != 0) o = cmul(o, g_tw[t * G * r]);
        Xs[PHY(base + i * S)] = o;
    }
}

template<int S, int G>
__device__ __forceinline__ void inv_stage(float2* Xs, int tid) {
    int blk, t;
    if (S == 256)      { blk = 0;         t = tid;      }
    else if (S == 16)  { blk = tid >> 4;  t = tid & 15; }
    else               { blk = tid;       t = 0;        }
    int base = blk * 16 * S + t;
    float2 v[16];
    #pragma unroll
    for (int i = 0; i < 16; i++) {
        int r = ((i & 3) << 2) | (i >> 2);
        float2 x = Xs[PHY(base + i * S)];
        if (S != 1 && r != 0) x = cmulc(x, g_tw[t * G * r]);
        v[i] = x;
    }
    sixteen_inv(v);
    #pragma unroll
    for (int q = 0; q < 16; q++) Xs[PHY(base + q * S)] = v[q];
}

// ---------------- twiddle init ----------------
__global__ void k_tw() {
    int m = blockIdx.x * blockDim.x + threadIdx.x;
    if (m < NS) {
        double ang = -2.0 * 3.14159265358979323846 * (double)m / (double)NS;
        g_tw[m] = make_float2((float)cos(ang), (float)sin(ang));
    }
}

// ---------------- transpose (B,S,C) -> scratch (B,C,S) ----------------
__global__ void k_t1(const float* __restrict__ in) {
    __shared__ float tile[32][33];
    int b  = blockIdx.z;
    int c0 = blockIdx.x * 32;
    int s0 = blockIdx.y * 32;
    #pragma unroll
    for (int i = threadIdx.y; i < 32; i += 8)
        tile[i][threadIdx.x] = in[((size_t)b * NS + (s0 + i)) * NC + (c0 + threadIdx.x)];
    __syncthreads();
    #pragma unroll
    for (int i = threadIdx.y; i < 32; i += 8)
        g_tr[((size_t)b * NC + (c0 + i)) * NS + (s0 + threadIdx.x)] = tile[threadIdx.x][i];
}

// ---------------- transpose scratch (B,C,S) -> out (B,S,C) ----------------
__global__ void k_t3(float* __restrict__ out) {
    __shared__ float tile[32][33];
    int b  = blockIdx.z;
    int c0 = blockIdx.x * 32;
    int s0 = blockIdx.y * 32;
    #pragma unroll
    for (int i = threadIdx.y; i < 32; i += 8)
        tile[i][threadIdx.x] = g_tr[((size_t)b * NC + (c0 + i)) * NS + (s0 + threadIdx.x)];
    __syncthreads();
    #pragma unroll
    for (int i = threadIdx.y; i < 32; i += 8)
        out[((size_t)b * NS + (s0 + i)) * NC + (c0 + threadIdx.x)] = tile[threadIdx.x][i];
}

// ---------------- paired-channel: FFT -> split -> top-64 -> recombine -> iFFT ----------------
__global__ __launch_bounds__(256) void k_fft() {
    __shared__ float2 X[NS];
    __shared__ unsigned hA[256], hB[256];
    __shared__ unsigned sPrefA, sPrefB, sNeedA, sNeedB;

    const int tid = threadIdx.x;
    const size_t row = (size_t)blockIdx.x * 2 * NS;
    const float4* a4 = (const float4*)(g_tr + row);
    const float4* b4 = (const float4*)(g_tr + row + NS);

    // load two real rows, pack z = a + i b
    #pragma unroll
    for (int i = tid; i < NS / 4; i += 256) {
        float4 av = a4[i], bv = b4[i];
        X[PHY(4 * i + 0)] = make_float2(av.x, bv.x);
        X[PHY(4 * i + 1)] = make_float2(av.y, bv.y);
        X[PHY(4 * i + 2)] = make_float2(av.z, bv.z);
        X[PHY(4 * i + 3)] = make_float2(av.w, bv.w);
    }
    if (tid == 0) { sPrefA = 0; sPrefB = 0; sNeedA = KTOP; sNeedB = KTOP; }
    __syncthreads();

    fwd_stage<256, 1>(X, tid);  __syncthreads();
    fwd_stage<16, 16>(X, tid);  __syncthreads();
    fwd_stage<1, 256>(X, tid);  __syncthreads();

    // split: A[k] -> logical pos drev4(k); B[k] -> logical pos drev4(4096-k); k=1..2047
    {
        int kb = ((tid & 31) << 6) | ((tid >> 5) << 3);
        #pragma unroll
        for (int m = 0; m < 8; m++) {
            int k = kb + m;
            if (k) {
                int p  = PHY(drev4(k));
                int pn = PHY(drev4(NS - k));
                float2 z = X[p], zn = X[pn];
                float2 A  = make_float2(0.5f * (z.x + zn.x), 0.5f * (z.y - zn.y));
                float2 Bc = make_float2(0.5f * (z.y + zn.y), 0.5f * (zn.x - z.x));
                X[p] = A; X[pn] = Bc;
            }
            // k==0 and k==2048 already store (A,B) packed as (re,im): no-op
        }
    }
    __syncthreads();

    // dual 4-pass radix select over |.|^2, position-ordered (coalesced)
    unsigned himask = 0u;
    for (int pass = 0; pass < 4; pass++) {
        const int shift = 24 - 8 * pass;
        hA[tid] = 0u; hB[tid] = 0u;
        __syncthreads();
        const unsigned pA = sPrefA, pB = sPrefB;
        #pragma unroll
        for (int p = tid; p < NS; p += 256) {
            int km = drev4(p);
            float2 v = X[PHY(p)];
            if (km == 0 || km == NS / 2) {
                unsigned ua = __float_as_uint(v.x * v.x);
                if ((ua & himask) == pA) atomicAdd(&hA[(ua >> shift) & 255], 1u);
                unsigned ub = __float_as_uint(v.y * v.y);
                if ((ub & himask) == pB) atomicAdd(&hB[(ub >> shift) & 255], 1u);
            } else {
                unsigned u = __float_as_uint(v.x * v.x + v.y * v.y);
                if (km < NS / 2) { if ((u & himask) == pA) atomicAdd(&hA[(u >> shift) & 255], 1u); }
                else             { if ((u & himask) == pB) atomicAdd(&hB[(u >> shift) & 255], 1u); }
            }
        }
        __syncthreads();
        if (tid == 0) {
            unsigned need = sNeedA, acc = 0;
            for (int bkt = 255; bkt >= 0; bkt--) {
                unsigned cnt = hA[bkt];
                if (acc + cnt >= need) { sNeedA = need - acc; sPrefA = pA | ((unsigned)bkt << shift); break; }
                acc += cnt;
            }
        }
        if (tid == 32) {
            unsigned need = sNeedB, acc = 0;
            for (int bkt = 255; bkt >= 0; bkt--) {
                unsigned cnt = hB[bkt];
                if (acc + cnt >= need) { sNeedB = need - acc; sPrefB = pB | ((unsigned)bkt << shift); break; }
                acc += cnt;
            }
        }
        himask = 0xFFFFFFFFu << shift;
        __syncthreads();
    }
    const float pivA = __uint_as_float(sPrefA);
    const float pivB = __uint_as_float(sPrefB);

    // mask + recombine Zf = Am + i*Bm (Hermitian pair written together)
    {
        int kb = ((tid & 31) << 6) | ((tid >> 5) << 3);
        #pragma unroll
        for (int m = 0; m < 8; m++) {
            int k = kb + m;
            if (k) {
                int p  = PHY(drev4(k));
                int pn = PHY(drev4(NS - k));
                float2 A = X[p], Bc = X[pn];
                float ma = A.x * A.x + A.y * A.y;
                float mb = Bc.x * Bc.x + Bc.y * Bc.y;
                if (ma < pivA) A  = make_float2(0.f, 0.f);
                if (mb < pivB) Bc = make_float2(0.f, 0.f);
                X[p]  = make_float2(A.x - Bc.y, A.y + Bc.x);
                X[pn] = make_float2(A.x + Bc.y, Bc.x - A.y);
            } else {
                // bin 0 and bin 2048 (both self-conjugate, stored packed (A,B))
                float2 v0 = X[PHY(0)];
                v0.x = (v0.x * v0.x >= pivA) ? v0.x : 0.f;
                v0.y = (v0.y * v0.y >= pivB) ? v0.y : 0.f;
                X[PHY(0)] = v0;
                int p2 = PHY(drev4(NS / 2));
                float2 v2 = X[p2];
                v2.x = (v2.x * v2.x >= pivA) ? v2.x : 0.f;
                v2.y = (v2.y * v2.y >= pivB) ? v2.y : 0.f;
                X[p2] = v2;
            }
        }
    }
    __syncthreads();

    inv_stage<1, 256>(X, tid);  __syncthreads();
    inv_stage<16, 16>(X, tid);  __syncthreads();
    inv_stage<256, 1>(X, tid);  __syncthreads();

    // store: real -> channel a, imag -> channel b, scaled 1/N
    const float invn = 1.0f / (float)NS;
    float4* ao = (float4*)(g_tr + row);
    float4* bo = (float4*)(g_tr + row + NS);
    #pragma unroll
    for (int i = tid; i < NS / 4; i += 256) {
        float2 v0 = X[PHY(4 * i + 0)];
        float2 v1 = X[PHY(4 * i + 1)];
        float2 v2 = X[PHY(4 * i + 2)];
        float2 v3 = X[PHY(4 * i + 3)];
        ao[i] = make_float4(v0.x * invn, v1.x * invn, v2.x * invn, v3.x * invn);
        bo[i] = make_float4(v0.y * invn, v1.y * invn, v2.y * invn, v3.y * invn);
    }
}

extern "C" void kernel_launch(void* const* d_in, const int* in_sizes, int n_in,
                              void* d_out, int out_size) {
    const float* in = (const float*)d_in[0];
    float* out = (float*)d_out;

    k_tw<<<(NS + 255) / 256, 256>>>();

    dim3 bt(32, 8);
    dim3 gt(NC / 32, NS / 32, NB);
    k_t1<<<gt, bt>>>(in);

    k_fft<<<NB * NC / 2, 256>>>();

    k_t3<<<gt, bt>>>(out);
}